// round 13
// baseline (speedup 1.0000x reference)
#include <cuda_runtime.h>

#define TPB  512
#define PPT  4
#define TILE (TPB * PPT)   // 2048 points per block

// Cell record (13 floats): 3 x float4 + 1 scalar
//  r0: ax, ay, bx, by
//  r1: cx, cy, ocx, ocy
//  r2: r*r, ecx, ecy, 1/erx
//  siery: 1/ery
// Edge deltas recomputed in registers with bit-identical __fsub_rn.

// Shade one cell, update best. Exact reference op order (no fma contraction).
// No validity mask: caller passes a duplicate cell when a neighbor is
// off-grid; re-shading the same cell is idempotent under max().
#define SHADE_CELL(cell)                                                       \
    do {                                                                       \
        int _c = (cell);                                                       \
        float4 r0  = rec4[_c * 3 + 0];                                         \
        float4 r1  = rec4[_c * 3 + 1];                                         \
        float4 r2v = rec4[_c * 3 + 2];                                         \
        float  iery = siery[_c];                                               \
        float d0x = __fsub_rn(r0.z, r0.x), d0y = __fsub_rn(r0.w, r0.y);        \
        float d1x = __fsub_rn(r1.x, r0.z), d1y = __fsub_rn(r1.y, r0.w);        \
        float d2x = __fsub_rn(r0.x, r1.x), d2y = __fsub_rn(r0.y, r1.y);        \
        float e0 = __fsub_rn(__fmul_rn(__fsub_rn(px, r0.x), d0y),              \
                             __fmul_rn(__fsub_rn(py, r0.y), d0x));             \
        float e1 = __fsub_rn(__fmul_rn(__fsub_rn(px, r0.z), d1y),              \
                             __fmul_rn(__fsub_rn(py, r0.w), d1x));             \
        float e2 = __fsub_rn(__fmul_rn(__fsub_rn(px, r1.x), d2y),              \
                             __fmul_rn(__fsub_rn(py, r1.y), d2x));             \
        float emin = fminf(fminf(e0, e1), e2);                                 \
        float emax = fmaxf(fmaxf(e0, e1), e2);                                 \
        bool tri_in = (emin >= 0.0f) || (emax <= 0.0f);                        \
        float dcx = __fsub_rn(px, r1.z), dcy = __fsub_rn(py, r1.w);            \
        bool circ_in =                                                         \
            __fadd_rn(__fmul_rn(dcx, dcx), __fmul_rn(dcy, dcy)) <= r2v.x;      \
        float xn = __fmul_rn(__fsub_rn(px, r2v.y), r2v.w);                     \
        float yn = __fmul_rn(__fsub_rn(py, r2v.z), iery);                      \
        bool ell_in =                                                          \
            __fadd_rn(__fmul_rn(xn, xn), __fmul_rn(yn, yn)) <= 1.0f;           \
        int c3 = _c * 3;                                                       \
        int cb = tri_in ? c3 : -1;                                             \
        cb = circ_in ? c3 + 1 : cb;                                            \
        cb = ell_in ? c3 + 2 : cb;                                             \
        best = best > cb ? best : cb;                                          \
    } while (0)

__global__ __launch_bounds__(TPB, 4)
void vg_kernel(const float* __restrict__ x, const float* __restrict__ p,
               float* __restrict__ out, int n)
{
    __shared__ float4 rec4[25 * 3];
    __shared__ float  siery[25];
    __shared__ float4 colors4[76];         // slot 0 = black; [1+s] = shape s rgb
    __shared__ float2 sp[TILE];            // (cell,quadrant)-sorted points
    __shared__ unsigned int stmp[TILE];    // key | rank<<8 | meta<<19 (staging)
    __shared__ unsigned int sinfo[TILE];   // orig(11b) | meta<<11
    __shared__ unsigned char sbest[TILE];  // winner+1 per ORIGINAL point
    __shared__ int hist[225];
    __shared__ int off[225];
    __shared__ int wsum[8];

    const int tid = threadIdx.x;

    if (tid < 25) {
        const float* q = p + tid * 28;
        rec4[tid * 3 + 0] = make_float4(q[1], q[2], q[3], q[4]);
        rec4[tid * 3 + 1] = make_float4(q[5], q[6], q[12], q[13]);
        rec4[tid * 3 + 2] = make_float4(__fmul_rn(q[14], q[14]),
                                        q[20], q[21], 1.0f / q[22]);
        siery[tid] = 1.0f / q[23];
    }
    if (tid < 76) {
        if (tid == 0) colors4[0] = make_float4(0.0f, 0.0f, 0.0f, 0.0f);
        else {
            int s = tid - 1;
            int c = s / 3, t = s % 3;
            int o = (t == 0) ? 8 : ((t == 1) ? 16 : 25);
            const float* q = p + c * 28 + o;
            colors4[tid] = make_float4(q[0], q[1], q[2], 0.0f);
        }
    }
    if (tid < 225) hist[tid] = 0;
    __syncthreads();

    const int base = blockIdx.x * TILE;

    // ---- Phase 1: vectorized load, integer classify, histogram ----
    // Thread t owns points {2t, 2t+1, TILE/2+2t, TILE/2+2t+1} of the tile
    // (two float4 = two point-pairs). Staging slots are thread-private, so
    // the remap is free; true original index is carried in the meta word.
    float2 pts[PPT];
    int    orig[PPT];
    {
        const float4* x4 = (const float4*)x;   // one float4 = 2 points
        int nv = n >> 1;                       // number of whole point-pairs
        int i0 = (base >> 1) + tid;            // pair index for pts[0..1]
        int i1 = i0 + (TILE >> 2);             // pair index for pts[2..3]
        float4 a = (i0 < nv) ? x4[i0] : make_float4(0.5f, 0.5f, 0.5f, 0.5f);
        float4 b = (i1 < nv) ? x4[i1] : make_float4(0.5f, 0.5f, 0.5f, 0.5f);
        pts[0] = make_float2(a.x, a.y);  orig[0] = 2 * tid;
        pts[1] = make_float2(a.z, a.w);  orig[1] = 2 * tid + 1;
        pts[2] = make_float2(b.x, b.y);  orig[2] = (TILE >> 1) + 2 * tid;
        pts[3] = make_float2(b.z, b.w);  orig[3] = (TILE >> 1) + 2 * tid + 1;
    }
#pragma unroll
    for (int k = 0; k < PPT; k++) {
        float2 pt = pts[k];
        // 1/16-cell fixed point. Neighbor needed only when the point is
        // within 0.4 cell-widths of a boundary; thresholds 7/16 and 9/16
        // bracket that with >=0.0375cw margin (>> any f32 rounding).
        int sx = (int)(pt.x * 80.0f); sx = sx < 0 ? 0 : (sx > 79 ? 79 : sx);
        int sy = (int)(pt.y * 80.0f); sy = sy < 0 ? 0 : (sy > 79 ? 79 : sy);
        int ci = sx >> 4, fx = sx & 15;
        int cj = sy >> 4, fy = sy & 15;
        int dxp = (fx <= 6) ? 0 : ((fx >= 9) ? 2 : 1);   // dxn+1
        int dyp = (fy <= 6) ? 0 : ((fy >= 9) ? 2 : 1);   // dyn+1
        int cc  = ci * 5 + cj;
        int key = cc * 9 + dxp * 3 + dyp;                // 0..224
        unsigned vx = (dxp != 1) && ((unsigned)(ci + dxp - 1) <= 4u);
        unsigned vy = (dyp != 1) && ((unsigned)(cj + dyp - 1) <= 4u);
        unsigned meta = (unsigned)cc | ((unsigned)dxp << 5) |
                        ((unsigned)dyp << 7) | (vx << 9) | (vy << 10);
        int rank = atomicAdd(&hist[key], 1);
        stmp[k * TPB + tid] = (unsigned)key | ((unsigned)rank << 8) | (meta << 19);
    }
    __syncthreads();

    // ---- Phase 2: exclusive scan of 225 bins (warps 0-7) ----
    {
        int v = 0, s = 0;
        if (tid < 256) {
            v = (tid < 225) ? hist[tid] : 0;
            s = v;
#pragma unroll
            for (int d = 1; d < 32; d <<= 1) {
                int t = __shfl_up_sync(0xffffffff, s, d);
                if ((tid & 31) >= d) s += t;
            }
            if ((tid & 31) == 31) wsum[tid >> 5] = s;
        }
        __syncthreads();
        if (tid < 8) {
            int w = wsum[tid];
            int sw = w;
#pragma unroll
            for (int d = 1; d < 8; d <<= 1) {
                int t = __shfl_up_sync(0xff, sw, d);
                if (tid >= d) sw += t;
            }
            wsum[tid] = sw - w;
        }
        __syncthreads();
        if (tid < 225) off[tid] = (s - v) + wsum[tid >> 5];
    }
    __syncthreads();

    // ---- Phase 3: scatter into (cell,quadrant)-sorted order ----
#pragma unroll
    for (int k = 0; k < PPT; k++) {
        unsigned m = stmp[k * TPB + tid];
        int pos = off[m & 255] + (int)((m >> 8) & 2047);
        sp[pos]    = pts[k];
        sinfo[pos] = (unsigned)orig[k] | ((m >> 19) << 11);
    }
    __syncthreads();

    // ---- Phase 4: uniform 4-cell shading (dup-clamped, flat) ----
#pragma unroll 1
    for (int k = 0; k < PPT; k++) {
        int li = k * TPB + tid;
        float2 pt = sp[li];
        const float px = pt.x, py = pt.y;
        unsigned m = sinfo[li];
        int po   = m & 2047;
        int cc   = (m >> 11) & 31;
        int dxn  = (int)((m >> 16) & 3) - 1;
        int dyn  = (int)((m >> 18) & 3) - 1;
        int ccx  = ((m >> 20) & 1) ? cc + dxn * 5 : cc;   // dup if off-grid
        int ccy  = ((m >> 21) & 1) ? cc + dyn     : cc;
        int ccxy = ccx + (ccy - cc);

        int best = -1;
        SHADE_CELL(cc);
        SHADE_CELL(ccx);
        SHADE_CELL(ccy);
        SHADE_CELL(ccxy);

        sbest[po] = (unsigned char)(best + 1);
    }
    __syncthreads();

    // ---- Phase 5: vectorized output (uchar4 + 3 x STG.128 per thread) ----
    {
        int gi0 = base + tid * 4;
        if (gi0 + 4 <= n) {
            uchar4 u = *(const uchar4*)(sbest + tid * 4);
            float4 C0 = colors4[u.x];
            float4 C1 = colors4[u.y];
            float4 C2 = colors4[u.z];
            float4 C3 = colors4[u.w];
            float4* dst = (float4*)(out + (size_t)gi0 * 3);
            dst[0] = make_float4(C0.x, C0.y, C0.z, C1.x);
            dst[1] = make_float4(C1.y, C1.z, C2.x, C2.y);
            dst[2] = make_float4(C2.z, C3.x, C3.y, C3.z);
        } else {
            for (int k = 0; k < 4; k++) {
                int gi = gi0 + k;
                if (gi < n) {
                    float4 C = colors4[sbest[tid * 4 + k]];
                    out[gi * 3 + 0] = C.x;
                    out[gi * 3 + 1] = C.y;
                    out[gi * 3 + 2] = C.z;
                }
            }
        }
    }
}

extern "C" void kernel_launch(void* const* d_in, const int* in_sizes, int n_in,
                              void* d_out, int out_size)
{
    // Identify inputs robustly: x has 2*N elements, p has 700
    int xi = 0, pi = 1;
    if (n_in >= 2 && in_sizes[0] < in_sizes[1]) { xi = 1; pi = 0; }
    const float* x = (const float*)d_in[xi];
    const float* p = (const float*)d_in[pi];
    float* out = (float*)d_out;

    int n = in_sizes[xi] / 2;
    int blocks = (n + TILE - 1) / TILE;
    vg_kernel<<<blocks, TPB>>>(x, p, out, n);
}

// round 15
// speedup vs baseline: 1.1250x; 1.1250x over previous
#include <cuda_runtime.h>

#define TPB  256
#define PPT  4
#define TILE (TPB * PPT)   // 1024 points per block

// Cell record (13 floats): 3 x float4 + 1 scalar
//  r0: ax, ay, bx, by
//  r1: cx, cy, ocx, ocy
//  r2: r*r, ecx, ecy, 1/erx
//  siery: 1/ery
// Edge deltas recomputed in registers with bit-identical __fsub_rn.

// Shade one cell, update best. Exact reference op order (no fma contraction).
// No validity mask: caller passes a duplicate cell when a neighbor is
// off-grid; re-shading the same cell is idempotent under max().
#define SHADE_CELL(cell)                                                       \
    do {                                                                       \
        int _c = (cell);                                                       \
        float4 r0  = rec4[_c * 3 + 0];                                         \
        float4 r1  = rec4[_c * 3 + 1];                                         \
        float4 r2v = rec4[_c * 3 + 2];                                         \
        float  iery = siery[_c];                                               \
        float d0x = __fsub_rn(r0.z, r0.x), d0y = __fsub_rn(r0.w, r0.y);        \
        float d1x = __fsub_rn(r1.x, r0.z), d1y = __fsub_rn(r1.y, r0.w);        \
        float d2x = __fsub_rn(r0.x, r1.x), d2y = __fsub_rn(r0.y, r1.y);        \
        float e0 = __fsub_rn(__fmul_rn(__fsub_rn(px, r0.x), d0y),              \
                             __fmul_rn(__fsub_rn(py, r0.y), d0x));             \
        float e1 = __fsub_rn(__fmul_rn(__fsub_rn(px, r0.z), d1y),              \
                             __fmul_rn(__fsub_rn(py, r0.w), d1x));             \
        float e2 = __fsub_rn(__fmul_rn(__fsub_rn(px, r1.x), d2y),              \
                             __fmul_rn(__fsub_rn(py, r1.y), d2x));             \
        float emin = fminf(fminf(e0, e1), e2);                                 \
        float emax = fmaxf(fmaxf(e0, e1), e2);                                 \
        bool tri_in = (emin >= 0.0f) || (emax <= 0.0f);                        \
        float dcx = __fsub_rn(px, r1.z), dcy = __fsub_rn(py, r1.w);            \
        bool circ_in =                                                         \
            __fadd_rn(__fmul_rn(dcx, dcx), __fmul_rn(dcy, dcy)) <= r2v.x;      \
        float xn = __fmul_rn(__fsub_rn(px, r2v.y), r2v.w);                     \
        float yn = __fmul_rn(__fsub_rn(py, r2v.z), iery);                      \
        bool ell_in =                                                          \
            __fadd_rn(__fmul_rn(xn, xn), __fmul_rn(yn, yn)) <= 1.0f;           \
        int c3 = _c * 3;                                                       \
        int cb = tri_in ? c3 : -1;                                             \
        cb = circ_in ? c3 + 1 : cb;                                            \
        cb = ell_in ? c3 + 2 : cb;                                             \
        best = best > cb ? best : cb;                                          \
    } while (0)

__global__ __launch_bounds__(TPB, 8)
void vg_kernel(const float* __restrict__ x, const float* __restrict__ p,
               float* __restrict__ out, int n)
{
    __shared__ float4 rec4[25 * 3];
    __shared__ float  siery[25];
    __shared__ float4 colors4[76];         // slot 0 = black; [1+s] = shape s rgb
    __shared__ float2 sp[TILE];            // (cell,quadrant)-sorted points
    __shared__ unsigned int stmp[TILE];    // key | rank<<8 | meta<<18 (staging)
    __shared__ unsigned int sinfo[TILE];   // orig(10b) | meta<<10
    __shared__ unsigned char sbest[TILE];  // winner+1 per ORIGINAL point
    __shared__ int hist[225];
    __shared__ int off[225];
    __shared__ int wsum[8];

    const int tid = threadIdx.x;

    if (tid < 25) {
        const float* q = p + tid * 28;
        rec4[tid * 3 + 0] = make_float4(q[1], q[2], q[3], q[4]);
        rec4[tid * 3 + 1] = make_float4(q[5], q[6], q[12], q[13]);
        rec4[tid * 3 + 2] = make_float4(__fmul_rn(q[14], q[14]),
                                        q[20], q[21], 1.0f / q[22]);
        siery[tid] = 1.0f / q[23];
    }
    if (tid < 76) {
        if (tid == 0) colors4[0] = make_float4(0.0f, 0.0f, 0.0f, 0.0f);
        else {
            int s = tid - 1;
            int c = s / 3, t = s % 3;
            int o = (t == 0) ? 8 : ((t == 1) ? 16 : 25);
            const float* q = p + c * 28 + o;
            colors4[tid] = make_float4(q[0], q[1], q[2], 0.0f);
        }
    }
    if (tid < 225) hist[tid] = 0;
    __syncthreads();

    const int base = blockIdx.x * TILE;

    // ---- Phase 1: vectorized load, integer classify, histogram ----
    // Thread t owns points {2t, 2t+1, TILE/2+2t, TILE/2+2t+1} of the tile
    // (two float4 = two point-pairs). Staging slots are thread-private, so
    // the remap is free; true original index rides through the sort.
    float2 pts[PPT];
    int    orig[PPT];
    {
        const float4* x4 = (const float4*)x;   // one float4 = 2 points
        int nv = n >> 1;                       // whole point-pairs
        int i0 = (base >> 1) + tid;            // pair for pts[0..1]
        int i1 = i0 + (TILE >> 2);             // pair for pts[2..3]
        float4 a = (i0 < nv) ? x4[i0] : make_float4(0.5f, 0.5f, 0.5f, 0.5f);
        float4 b = (i1 < nv) ? x4[i1] : make_float4(0.5f, 0.5f, 0.5f, 0.5f);
        pts[0] = make_float2(a.x, a.y);  orig[0] = 2 * tid;
        pts[1] = make_float2(a.z, a.w);  orig[1] = 2 * tid + 1;
        pts[2] = make_float2(b.x, b.y);  orig[2] = (TILE >> 1) + 2 * tid;
        pts[3] = make_float2(b.z, b.w);  orig[3] = (TILE >> 1) + 2 * tid + 1;
    }
#pragma unroll
    for (int k = 0; k < PPT; k++) {
        float2 pt = pts[k];
        // 1/16-cell fixed point. Neighbor needed only when the point is
        // within 0.4 cell-widths of a boundary; thresholds 7/16 and 9/16
        // bracket that with >=0.0375cw margin (>> any f32 rounding).
        int sx = (int)(pt.x * 80.0f); sx = sx < 0 ? 0 : (sx > 79 ? 79 : sx);
        int sy = (int)(pt.y * 80.0f); sy = sy < 0 ? 0 : (sy > 79 ? 79 : sy);
        int ci = sx >> 4, fx = sx & 15;
        int cj = sy >> 4, fy = sy & 15;
        int dxp = (fx <= 6) ? 0 : ((fx >= 9) ? 2 : 1);   // dxn+1
        int dyp = (fy <= 6) ? 0 : ((fy >= 9) ? 2 : 1);   // dyn+1
        int cc  = ci * 5 + cj;
        int key = cc * 9 + dxp * 3 + dyp;                // 0..224
        unsigned vx = (dxp != 1) && ((unsigned)(ci + dxp - 1) <= 4u);
        unsigned vy = (dyp != 1) && ((unsigned)(cj + dyp - 1) <= 4u);
        unsigned meta = (unsigned)cc | ((unsigned)dxp << 5) |
                        ((unsigned)dyp << 7) | (vx << 9) | (vy << 10);
        int rank = atomicAdd(&hist[key], 1);
        stmp[k * TPB + tid] = (unsigned)key | ((unsigned)rank << 8) | (meta << 18);
    }
    __syncthreads();

    // ---- Phase 2: exclusive scan of 225 bins (two-level shuffle scan) ----
    {
        int v = (tid < 225) ? hist[tid] : 0;
        int s = v;
#pragma unroll
        for (int d = 1; d < 32; d <<= 1) {
            int t = __shfl_up_sync(0xffffffff, s, d);
            if ((tid & 31) >= d) s += t;
        }
        if ((tid & 31) == 31) wsum[tid >> 5] = s;
        __syncthreads();
        if (tid < 8) {
            int w = wsum[tid];
            int sw = w;
#pragma unroll
            for (int d = 1; d < 8; d <<= 1) {
                int t = __shfl_up_sync(0xff, sw, d);
                if (tid >= d) sw += t;
            }
            wsum[tid] = sw - w;
        }
        __syncthreads();
        if (tid < 225) off[tid] = (s - v) + wsum[tid >> 5];
    }
    __syncthreads();

    // ---- Phase 3: scatter into (cell,quadrant)-sorted order ----
#pragma unroll
    for (int k = 0; k < PPT; k++) {
        unsigned m = stmp[k * TPB + tid];
        int pos = off[m & 255] + (int)((m >> 8) & 1023);
        sp[pos]    = pts[k];
        sinfo[pos] = (unsigned)orig[k] | ((m >> 18) << 10);
    }
    __syncthreads();

    // ---- Phase 4: uniform 4-cell shading (dup-clamped, flat) ----
#pragma unroll 1
    for (int k = 0; k < PPT; k++) {
        int li = k * TPB + tid;
        float2 pt = sp[li];
        const float px = pt.x, py = pt.y;
        unsigned m = sinfo[li];
        int po   = m & 1023;
        int cc   = (m >> 10) & 31;
        int dxn  = (int)((m >> 15) & 3) - 1;
        int dyn  = (int)((m >> 17) & 3) - 1;
        int ccx  = ((m >> 19) & 1) ? cc + dxn * 5 : cc;   // dup if off-grid
        int ccy  = ((m >> 20) & 1) ? cc + dyn     : cc;
        int ccxy = ccx + (ccy - cc);

        int best = -1;
        SHADE_CELL(cc);
        SHADE_CELL(ccx);
        SHADE_CELL(ccy);
        SHADE_CELL(ccxy);

        sbest[po] = (unsigned char)(best + 1);
    }
    __syncthreads();

    // ---- Phase 5: vectorized output (uchar4 + 3 x STG.128 per thread) ----
    {
        int gi0 = base + tid * 4;
        if (gi0 + 4 <= n) {
            uchar4 u = *(const uchar4*)(sbest + tid * 4);
            float4 C0 = colors4[u.x];
            float4 C1 = colors4[u.y];
            float4 C2 = colors4[u.z];
            float4 C3 = colors4[u.w];
            float4* dst = (float4*)(out + (size_t)gi0 * 3);
            dst[0] = make_float4(C0.x, C0.y, C0.z, C1.x);
            dst[1] = make_float4(C1.y, C1.z, C2.x, C2.y);
            dst[2] = make_float4(C2.z, C3.x, C3.y, C3.z);
        } else {
            for (int k = 0; k < 4; k++) {
                int gi = gi0 + k;
                if (gi < n) {
                    float4 C = colors4[sbest[tid * 4 + k]];
                    out[gi * 3 + 0] = C.x;
                    out[gi * 3 + 1] = C.y;
                    out[gi * 3 + 2] = C.z;
                }
            }
        }
    }
}

extern "C" void kernel_launch(void* const* d_in, const int* in_sizes, int n_in,
                              void* d_out, int out_size)
{
    // Identify inputs robustly: x has 2*N elements, p has 700
    int xi = 0, pi = 1;
    if (n_in >= 2 && in_sizes[0] < in_sizes[1]) { xi = 1; pi = 0; }
    const float* x = (const float*)d_in[xi];
    const float* p = (const float*)d_in[pi];
    float* out = (float*)d_out;

    int n = in_sizes[xi] / 2;
    int blocks = (n + TILE - 1) / TILE;
    vg_kernel<<<blocks, TPB>>>(x, p, out, n);
}

// round 16
// speedup vs baseline: 1.4132x; 1.2562x over previous
#include <cuda_runtime.h>

#define TPB  256
#define PPT  4
#define TILE (TPB * PPT)   // 1024 points per block
#define G    256           // LUT grid resolution

// Winner LUT: g_lut[sx*G+sy] = winner+1 (0 = black) if the whole cell provably
// has a constant winner, else 255 (ambiguous -> exact slow path).
__device__ unsigned char g_lut[G * G];

// ---------------------------------------------------------------------------
// Interval helpers (setup kernel only; conservative, margins >> f32 rounding)
// ---------------------------------------------------------------------------
__device__ __forceinline__ void imul(float lo, float hi, float c,
                                     float& rlo, float& rhi) {
    float a = lo * c, b = hi * c;
    rlo = fminf(a, b); rhi = fmaxf(a, b);
}
__device__ __forceinline__ void isq(float lo, float hi,
                                    float& rlo, float& rhi) {
    float a = lo * lo, b = hi * hi;
    rlo = (lo <= 0.0f && hi >= 0.0f) ? 0.0f : fminf(a, b);
    rhi = fmaxf(a, b);
}

// ---------------------------------------------------------------------------
// Setup: build the winner LUT with conservative interval tests
// ---------------------------------------------------------------------------
__global__ void lut_kernel(const float* __restrict__ p)
{
    int cid = blockIdx.x * blockDim.x + threadIdx.x;
    if (cid >= G * G) return;
    int sx = cid >> 8, sy = cid & (G - 1);

    const float inv = 1.0f / (float)G;
    // Rect expanded by 1e-6 to cover point->cell assignment rounding slop.
    float xlo = sx * inv - 1e-6f, xhi = (sx + 1) * inv + 1e-6f;
    float ylo = sy * inv - 1e-6f, yhi = (sy + 1) * inv + 1e-6f;

    // Candidate macro cells: shapes reach <= 0.08 (+f32 slop) outside their
    // cell; margin 0.0812 guarantees non-candidates are outside everywhere
    // in this rect.
    int i0 = (int)floorf((xlo - 0.0812f) * 5.0f); i0 = i0 < 0 ? 0 : i0;
    int i1 = (int)floorf((xhi + 0.0812f) * 5.0f); i1 = i1 > 4 ? 4 : i1;
    int j0 = (int)floorf((ylo - 0.0812f) * 5.0f); j0 = j0 < 0 ? 0 : j0;
    int j1 = (int)floorf((yhi + 0.0812f) * 5.0f); j1 = j1 > 4 ? 4 : j1;

    const float D = 2e-6f;   // absolute slack >> accumulated f32 rounding
    int best = -1, amb = -1;

    for (int i = i0; i <= i1; i++) {
        for (int j = j0; j <= j1; j++) {
            int cell = i * 5 + j;
            const float* q = p + cell * 28;
            int c3 = cell * 3;

            // ---- triangle ----
            {
                float ax = q[1], ay = q[2], bx = q[3], by = q[4];
                float cx = q[5], cy = q[6];
                float vx[3] = {ax, bx, cx}, vy[3] = {ay, by, cy};
                float dx[3] = {bx - ax, cx - bx, ax - cx};
                float dy[3] = {by - ay, cy - by, ay - cy};
                int npos = 0, nneg = 0;
                for (int e = 0; e < 3; e++) {
                    float alo, ahi, blo, bhi;
                    imul(xlo - vx[e], xhi - vx[e], dy[e], alo, ahi);
                    imul(ylo - vy[e], yhi - vy[e], dx[e], blo, bhi);
                    float elo = alo - bhi - D, ehi = ahi - blo + D;
                    if (elo > 0.0f) npos++;
                    else if (ehi < 0.0f) nneg++;
                }
                if (npos == 3 || nneg == 3)      best = max(best, c3);
                else if (!(npos >= 1 && nneg >= 1)) amb = max(amb, c3);
            }
            // ---- circle ----
            {
                float ox = q[12], oy = q[13], r = q[14];
                float r2 = r * r;
                float ulo, uhi, vlo, vhi;
                isq(xlo - ox, xhi - ox, ulo, uhi);
                isq(ylo - oy, yhi - oy, vlo, vhi);
                float glo = ulo + vlo - r2 - D, ghi = uhi + vhi - r2 + D;
                if (ghi <= 0.0f)      best = max(best, c3 + 1);
                else if (!(glo > 0.0f)) amb = max(amb, c3 + 1);
            }
            // ---- ellipse ----
            {
                float ex = q[20], ey = q[21];
                float irx = 1.0f / q[22], iry = 1.0f / q[23];
                float alo, ahi, blo, bhi, slo, shi, tlo, thi;
                imul(xlo - ex, xhi - ex, irx, alo, ahi); isq(alo, ahi, slo, shi);
                imul(ylo - ey, yhi - ey, iry, blo, bhi); isq(blo, bhi, tlo, thi);
                float glo = slo + tlo - 1.0f - D, ghi = shi + thi - 1.0f + D;
                if (ghi <= 0.0f)      best = max(best, c3 + 2);
                else if (!(glo > 0.0f)) amb = max(amb, c3 + 2);
            }
        }
    }
    g_lut[cid] = (amb <= best) ? (unsigned char)(best + 1)
                               : (unsigned char)255;
}

// ---------------------------------------------------------------------------
// Main kernel: LUT fast path + exact compacted slow path (R11 math, bit-exact)
// ---------------------------------------------------------------------------
// Cell record (13 floats): 3 x float4 + 1 scalar
//  r0: ax, ay, bx, by
//  r1: cx, cy, ocx, ocy
//  r2: r*r, ecx, ecy, 1/erx
//  siery: 1/ery
#define SHADE_CELL(cell)                                                       \
    do {                                                                       \
        int _c = (cell);                                                       \
        float4 r0  = rec4[_c * 3 + 0];                                         \
        float4 r1  = rec4[_c * 3 + 1];                                         \
        float4 r2v = rec4[_c * 3 + 2];                                         \
        float  iery = siery[_c];                                               \
        float d0x = __fsub_rn(r0.z, r0.x), d0y = __fsub_rn(r0.w, r0.y);        \
        float d1x = __fsub_rn(r1.x, r0.z), d1y = __fsub_rn(r1.y, r0.w);        \
        float d2x = __fsub_rn(r0.x, r1.x), d2y = __fsub_rn(r0.y, r1.y);        \
        float e0 = __fsub_rn(__fmul_rn(__fsub_rn(px, r0.x), d0y),              \
                             __fmul_rn(__fsub_rn(py, r0.y), d0x));             \
        float e1 = __fsub_rn(__fmul_rn(__fsub_rn(px, r0.z), d1y),              \
                             __fmul_rn(__fsub_rn(py, r0.w), d1x));             \
        float e2 = __fsub_rn(__fmul_rn(__fsub_rn(px, r1.x), d2y),              \
                             __fmul_rn(__fsub_rn(py, r1.y), d2x));             \
        float emin = fminf(fminf(e0, e1), e2);                                 \
        float emax = fmaxf(fmaxf(e0, e1), e2);                                 \
        bool tri_in = (emin >= 0.0f) || (emax <= 0.0f);                        \
        float dcx = __fsub_rn(px, r1.z), dcy = __fsub_rn(py, r1.w);            \
        bool circ_in =                                                         \
            __fadd_rn(__fmul_rn(dcx, dcx), __fmul_rn(dcy, dcy)) <= r2v.x;      \
        float xn = __fmul_rn(__fsub_rn(px, r2v.y), r2v.w);                     \
        float yn = __fmul_rn(__fsub_rn(py, r2v.z), iery);                      \
        bool ell_in =                                                          \
            __fadd_rn(__fmul_rn(xn, xn), __fmul_rn(yn, yn)) <= 1.0f;           \
        int c3 = _c * 3;                                                       \
        int cb = tri_in ? c3 : -1;                                             \
        cb = circ_in ? c3 + 1 : cb;                                            \
        cb = ell_in ? c3 + 2 : cb;                                             \
        best = best > cb ? best : cb;                                          \
    } while (0)

__global__ __launch_bounds__(TPB, 8)
void vg_kernel(const float* __restrict__ x, const float* __restrict__ p,
               float* __restrict__ out, int n)
{
    __shared__ float4 rec4[25 * 3];
    __shared__ float  siery[25];
    __shared__ float4 colors4[76];         // slot 0 = black
    __shared__ unsigned char sbest[TILE];  // winner+1 per tile point
    __shared__ float2 qpt[TILE];           // ambiguous-point queue
    __shared__ unsigned short qli[TILE];
    __shared__ int qcnt;

    const int tid = threadIdx.x;

    if (tid < 25) {
        const float* q = p + tid * 28;
        rec4[tid * 3 + 0] = make_float4(q[1], q[2], q[3], q[4]);
        rec4[tid * 3 + 1] = make_float4(q[5], q[6], q[12], q[13]);
        rec4[tid * 3 + 2] = make_float4(__fmul_rn(q[14], q[14]),
                                        q[20], q[21], 1.0f / q[22]);
        siery[tid] = 1.0f / q[23];
    }
    if (tid < 76) {
        if (tid == 0) colors4[0] = make_float4(0.0f, 0.0f, 0.0f, 0.0f);
        else {
            int s = tid - 1;
            int c = s / 3, t = s % 3;
            int o = (t == 0) ? 8 : ((t == 1) ? 16 : 25);
            const float* q = p + c * 28 + o;
            colors4[tid] = make_float4(q[0], q[1], q[2], 0.0f);
        }
    }
    if (tid == 0) qcnt = 0;
    __syncthreads();

    const int base = blockIdx.x * TILE;

    // ---- Fast path: LUT lookup; ambiguous points go to the queue ----
    {
        const float4* x4 = (const float4*)x;   // one float4 = 2 points
        int nv = n >> 1;
        int i0 = (base >> 1) + tid;
        int i1 = i0 + (TILE >> 2);
        float4 a = (i0 < nv) ? x4[i0] : make_float4(0.5f, 0.5f, 0.5f, 0.5f);
        float4 b = (i1 < nv) ? x4[i1] : make_float4(0.5f, 0.5f, 0.5f, 0.5f);
        float2 pts[PPT];
        int    orig[PPT];
        pts[0] = make_float2(a.x, a.y);  orig[0] = 2 * tid;
        pts[1] = make_float2(a.z, a.w);  orig[1] = 2 * tid + 1;
        pts[2] = make_float2(b.x, b.y);  orig[2] = (TILE >> 1) + 2 * tid;
        pts[3] = make_float2(b.z, b.w);  orig[3] = (TILE >> 1) + 2 * tid + 1;

#pragma unroll
        for (int k = 0; k < PPT; k++) {
            float2 pt = pts[k];
            int sx = (int)(pt.x * 256.0f); sx = sx < 0 ? 0 : (sx > 255 ? 255 : sx);
            int sy = (int)(pt.y * 256.0f); sy = sy < 0 ? 0 : (sy > 255 ? 255 : sy);
            unsigned w = g_lut[(sx << 8) | sy];
            if (w == 255u) {
                int qi = atomicAdd(&qcnt, 1);
                qpt[qi] = pt;
                qli[qi] = (unsigned short)orig[k];
                w = 0u;
            }
            sbest[orig[k]] = (unsigned char)w;
        }
    }
    __syncthreads();

    // ---- Slow path: exact shading for ambiguous points (R11 code) ----
    {
        int qn = qcnt;
        for (int i = tid; i < qn; i += TPB) {
            float2 pt = qpt[i];
            const float px = pt.x, py = pt.y;
            // 1/16-cell classifier (validated): thresholds 7/16 and 9/16
            // bracket the true 0.4 cell-width shape overhang.
            int sx = (int)(px * 80.0f); sx = sx < 0 ? 0 : (sx > 79 ? 79 : sx);
            int sy = (int)(py * 80.0f); sy = sy < 0 ? 0 : (sy > 79 ? 79 : sy);
            int ci = sx >> 4, fx = sx & 15;
            int cj = sy >> 4, fy = sy & 15;
            int dxn = (fx <= 6) ? -1 : ((fx >= 9) ? 1 : 0);
            int dyn = (fy <= 6) ? -1 : ((fy >= 9) ? 1 : 0);
            int cc = ci * 5 + cj;
            int i2 = ci + dxn, j2 = cj + dyn;
            int ccx  = ((unsigned)i2 <= 4u) ? cc + dxn * 5 : cc;  // dup-clamp
            int ccy  = ((unsigned)j2 <= 4u) ? cc + dyn     : cc;
            int ccxy = ccx + (ccy - cc);

            int best = -1;
            SHADE_CELL(cc);
            SHADE_CELL(ccx);
            SHADE_CELL(ccy);
            SHADE_CELL(ccxy);

            sbest[qli[i]] = (unsigned char)(best + 1);
        }
    }
    __syncthreads();

    // ---- Output: uchar4 winners -> 3 x STG.128 per thread ----
    {
        int gi0 = base + tid * 4;
        if (gi0 + 4 <= n) {
            uchar4 u = *(const uchar4*)(sbest + tid * 4);
            float4 C0 = colors4[u.x];
            float4 C1 = colors4[u.y];
            float4 C2 = colors4[u.z];
            float4 C3 = colors4[u.w];
            float4* dst = (float4*)(out + (size_t)gi0 * 3);
            dst[0] = make_float4(C0.x, C0.y, C0.z, C1.x);
            dst[1] = make_float4(C1.y, C1.z, C2.x, C2.y);
            dst[2] = make_float4(C2.z, C3.x, C3.y, C3.z);
        } else {
            for (int k = 0; k < 4; k++) {
                int gi = gi0 + k;
                if (gi < n) {
                    float4 C = colors4[sbest[tid * 4 + k]];
                    out[gi * 3 + 0] = C.x;
                    out[gi * 3 + 1] = C.y;
                    out[gi * 3 + 2] = C.z;
                }
            }
        }
    }
}

extern "C" void kernel_launch(void* const* d_in, const int* in_sizes, int n_in,
                              void* d_out, int out_size)
{
    // Identify inputs robustly: x has 2*N elements, p has 700
    int xi = 0, pi = 1;
    if (n_in >= 2 && in_sizes[0] < in_sizes[1]) { xi = 1; pi = 0; }
    const float* x = (const float*)d_in[xi];
    const float* p = (const float*)d_in[pi];
    float* out = (float*)d_out;

    int n = in_sizes[xi] / 2;

    lut_kernel<<<(G * G + 255) / 256, 256>>>(p);
    int blocks = (n + TILE - 1) / TILE;
    vg_kernel<<<blocks, TPB>>>(x, p, out, n);
}